// round 2
// baseline (speedup 1.0000x reference)
#include <cuda_runtime.h>
#include <cstddef>

// Problem: B=64, n_l=512, n_h=32, d_l=16, d_h=32
#define Bsz 64
#define NLc 512
#define NHc 32
#define DLc 16
#define KLc 1024   // NH*DH
#define INV_SCALE 0.17677669529663687f  // 1/sqrt(32)

// Static scratch (no allocations allowed)
__device__ float g_S[Bsz * KLc];          // S[b][k*32+l]
__device__ float g_C[Bsz * NLc * NHc];    // C[b][i][k]
__device__ float g_Uh[Bsz * KLc];         // U_h accumulator

// Packed fp32x2 FMA (sm_100+): 2x fp32 FMA throughput
__device__ __forceinline__ float2 ffma2(float2 a, float2 b, float2 c) {
    float2 d;
    asm("{\n\t"
        ".reg .b64 ra, rb, rc, rd;\n\t"
        "mov.b64 ra, {%2, %3};\n\t"
        "mov.b64 rb, {%4, %5};\n\t"
        "mov.b64 rc, {%6, %7};\n\t"
        "fma.rn.f32x2 rd, ra, rb, rc;\n\t"
        "mov.b64 {%0, %1}, rd;\n\t"
        "}"
        : "=f"(d.x), "=f"(d.y)
        : "f"(a.x), "f"(a.y), "f"(b.x), "f"(b.y), "f"(c.x), "f"(c.y));
    return d;
}

// ---------------------------------------------------------------------------
// Zero accumulators (replayed each graph launch)
// ---------------------------------------------------------------------------
__global__ void k_zero() {
    const int t = blockIdx.x * blockDim.x + threadIdx.x;  // 0..16383
    const float4 z = make_float4(0.f, 0.f, 0.f, 0.f);
    *reinterpret_cast<float4*>(g_S + (size_t)t * 4) = z;
    *reinterpret_cast<float4*>(g_Uh + (size_t)t * 4) = z;
}

// ---------------------------------------------------------------------------
// Pass 1: S[b][k*32+l] = sum_{i,j} U[b,i*16+j] * W[i,k,j,l]
// Grid (8 col-tiles of 128, 16 i-chunks of 32), 256 thr, thread tile 8b x 4c.
// ---------------------------------------------------------------------------
__global__ void __launch_bounds__(256) k_pass1(const float* __restrict__ U,
                                               const float* __restrict__ W) {
    __shared__ float Us[Bsz][DLc];     // 64 x 16
    __shared__ float Ws[DLc][132];     // 16 x 128 (padded)
    const int tx = threadIdx.x;
    const int cg = tx & 31;            // col-group: 4 cols each
    const int bg = tx >> 5;            // b-group: 8 b each (warp-uniform)
    const int k0 = blockIdx.x * 4;     // k base (cols k0*32 .. k0*32+127)
    const int i0 = blockIdx.y * 32;

    float2 acc[8][2];
#pragma unroll
    for (int bb = 0; bb < 8; bb++) {
        acc[bb][0] = make_float2(0.f, 0.f);
        acc[bb][1] = make_float2(0.f, 0.f);
    }

    for (int it = 0; it < 32; it++) {
        const int i = i0 + it;
        __syncthreads();
        {   // U tile: 64x16 = 256 float4, one per thread
            const int b = tx >> 2, j4 = (tx & 3) * 4;
            *reinterpret_cast<float4*>(&Us[b][j4]) =
                *reinterpret_cast<const float4*>(U + (size_t)b * 8192 + (size_t)i * 16 + j4);
        }
        {   // W tile: 16x128 = 512 float4, two per thread (coalesced)
            const float* Wi = W + (size_t)i * 16384 + (size_t)k0 * 512;
#pragma unroll
            for (int r = 0; r < 2; r++) {
                const int v = tx + r * 256;       // float4 index 0..511
                const int kk = v >> 7;            // 0..3
                const int rem = v & 127;
                const int j = rem >> 3;
                const int l4 = (rem & 7) * 4;
                *reinterpret_cast<float4*>(&Ws[j][kk * 32 + l4]) =
                    *reinterpret_cast<const float4*>(Wi + kk * 512 + j * 32 + l4);
            }
        }
        __syncthreads();
#pragma unroll
        for (int j0 = 0; j0 < 16; j0 += 4) {
            float4 wv[4];
#pragma unroll
            for (int jj = 0; jj < 4; jj++)
                wv[jj] = *reinterpret_cast<const float4*>(&Ws[j0 + jj][cg * 4]);
#pragma unroll
            for (int bb = 0; bb < 8; bb++) {
                const float4 uv = *reinterpret_cast<const float4*>(&Us[bg * 8 + bb][j0]);
                const float uj[4] = {uv.x, uv.y, uv.z, uv.w};
#pragma unroll
                for (int jj = 0; jj < 4; jj++) {
                    const float2 us = make_float2(uj[jj], uj[jj]);
                    acc[bb][0] = ffma2(us, make_float2(wv[jj].x, wv[jj].y), acc[bb][0]);
                    acc[bb][1] = ffma2(us, make_float2(wv[jj].z, wv[jj].w), acc[bb][1]);
                }
            }
        }
    }
#pragma unroll
    for (int bb = 0; bb < 8; bb++) {
        float* dst = g_S + (size_t)(bg * 8 + bb) * KLc + k0 * 32 + cg * 4;
        atomicAdd(dst + 0, acc[bb][0].x);
        atomicAdd(dst + 1, acc[bb][0].y);
        atomicAdd(dst + 2, acc[bb][1].x);
        atomicAdd(dst + 3, acc[bb][1].y);
    }
}

// ---------------------------------------------------------------------------
// Pass 2a: per i: recompute u_hat[b,k,:], A_sum[b,k] = dot(u_hat, S[b,k,:]),
// softmax over k -> C[b,i,k]. W[i] staged in dynamic SMEM (padded).
// ---------------------------------------------------------------------------
#define WPAD 36
#define WS2A (512 * WPAD)                            // (j*32+k) rows x WPAD
#define SM2A_FLOATS (WS2A + Bsz * DLc + Bsz * NHc)   // 18432+1024+2048
#define SM2A_BYTES (SM2A_FLOATS * 4)                 // 86016 B

__global__ void __launch_bounds__(256) k_pass2a(const float* __restrict__ U,
                                                const float* __restrict__ W) {
    extern __shared__ float sm[];
    float* Ws  = sm;                      // [(j*32 + k)*WPAD + l]
    float* Us  = sm + WS2A;               // [b*16 + j]
    float* Asm = Us + Bsz * DLc;          // [b*32 + k]
    const int tx = threadIdx.x;
    const int i = blockIdx.x;

    {   // W[i]: 16384 floats = 4096 float4, 16 per thread
        const float* Wi = W + (size_t)i * 16384;
#pragma unroll
        for (int r = 0; r < 16; r++) {
            const int g = (tx + r * 256) * 4;   // float offset in W[i]
            const int k = g >> 9;
            const int j = (g >> 5) & 15;
            const int l = g & 31;
            *reinterpret_cast<float4*>(Ws + (j * 32 + k) * WPAD + l) =
                *reinterpret_cast<const float4*>(Wi + g);
        }
    }
    {
        const int b = tx >> 2, j4 = (tx & 3) * 4;
        *reinterpret_cast<float4*>(Us + b * 16 + j4) =
            *reinterpret_cast<const float4*>(U + (size_t)b * 8192 + (size_t)i * 16 + j4);
    }
    __syncthreads();

    const int kk = tx & 15;
    const int bg = tx >> 4;   // 16 groups of 4 b
#pragma unroll
    for (int kh = 0; kh < 2; kh++) {
        const int k = kk + kh * 16;
        float a[4] = {0.f, 0.f, 0.f, 0.f};
#pragma unroll
        for (int lh = 0; lh < 2; lh++) {
            const int l0 = lh * 16;
            float2 uh[4][8];
#pragma unroll
            for (int bb = 0; bb < 4; bb++)
#pragma unroll
                for (int p = 0; p < 8; p++) uh[bb][p] = make_float2(0.f, 0.f);
#pragma unroll
            for (int j = 0; j < 16; j++) {
                const float* wrow = Ws + (j * 32 + k) * WPAD + l0;
                float2 wp[8];
#pragma unroll
                for (int q = 0; q < 4; q++) {
                    const float4 w4 = *reinterpret_cast<const float4*>(wrow + q * 4);
                    wp[2 * q]     = make_float2(w4.x, w4.y);
                    wp[2 * q + 1] = make_float2(w4.z, w4.w);
                }
#pragma unroll
                for (int bb = 0; bb < 4; bb++) {
                    const float u = Us[(bg * 4 + bb) * 16 + j];
                    const float2 us = make_float2(u, u);
#pragma unroll
                    for (int p = 0; p < 8; p++) uh[bb][p] = ffma2(us, wp[p], uh[bb][p]);
                }
            }
#pragma unroll
            for (int bb = 0; bb < 4; bb++) {
                const float* Sp = g_S + (size_t)(bg * 4 + bb) * KLc + k * 32 + l0;
#pragma unroll
                for (int q = 0; q < 4; q++) {
                    const float4 s4 = *reinterpret_cast<const float4*>(Sp + q * 4);
                    a[bb] += uh[bb][2 * q].x * s4.x + uh[bb][2 * q].y * s4.y
                           + uh[bb][2 * q + 1].x * s4.z + uh[bb][2 * q + 1].y * s4.w;
                }
            }
        }
#pragma unroll
        for (int bb = 0; bb < 4; bb++) Asm[(bg * 4 + bb) * 32 + k] = a[bb];
    }
    __syncthreads();

    if (tx < Bsz) {
        const int b = tx;
        float v[32];
        float m = -3.4e38f;
#pragma unroll
        for (int k = 0; k < 32; k++) { v[k] = Asm[b * 32 + k]; m = fmaxf(m, v[k]); }
        float s = 0.f;
#pragma unroll
        for (int k = 0; k < 32; k++) { v[k] = __expf((v[k] - m) * INV_SCALE); s += v[k]; }
        const float inv = 1.f / s;
        float* Cp = g_C + ((size_t)b * NLc + i) * NHc;
#pragma unroll
        for (int k = 0; k < 32; k++) Cp[k] = v[k] * inv;
    }
}

// ---------------------------------------------------------------------------
// Pass 2b: U_h[b][k*32+l] = sum_i C[b,i,k] * u_hat[b,i,k,l]
// Pass-1 skeleton with per-i C-weighting.
// ---------------------------------------------------------------------------
__global__ void __launch_bounds__(256) k_pass2b(const float* __restrict__ U,
                                                const float* __restrict__ W) {
    __shared__ float Us[Bsz][DLc];
    __shared__ float Ws[DLc][132];
    __shared__ float Cs[Bsz][4];
    const int tx = threadIdx.x;
    const int cg = tx & 31;
    const int bg = tx >> 5;
    const int k0 = blockIdx.x * 4;
    const int i0 = blockIdx.y * 32;
    const int kq = cg >> 3;            // which of the 4 k this thread's cols use

    float2 acc[8][2];
#pragma unroll
    for (int bb = 0; bb < 8; bb++) {
        acc[bb][0] = make_float2(0.f, 0.f);
        acc[bb][1] = make_float2(0.f, 0.f);
    }

    for (int it = 0; it < 32; it++) {
        const int i = i0 + it;
        __syncthreads();
        {
            const int b = tx >> 2, j4 = (tx & 3) * 4;
            *reinterpret_cast<float4*>(&Us[b][j4]) =
                *reinterpret_cast<const float4*>(U + (size_t)b * 8192 + (size_t)i * 16 + j4);
        }
        {
            const float* Wi = W + (size_t)i * 16384 + (size_t)k0 * 512;
#pragma unroll
            for (int r = 0; r < 2; r++) {
                const int v = tx + r * 256;
                const int kk = v >> 7;
                const int rem = v & 127;
                const int j = rem >> 3;
                const int l4 = (rem & 7) * 4;
                *reinterpret_cast<float4*>(&Ws[j][kk * 32 + l4]) =
                    *reinterpret_cast<const float4*>(Wi + kk * 512 + j * 32 + l4);
            }
        }
        {   // C[b][i][k0..k0+3] for all b: 256 values, one per thread
            const int b2 = tx >> 2, kq2 = tx & 3;
            Cs[b2][kq2] = g_C[((size_t)b2 * NLc + i) * NHc + k0 + kq2];
        }
        __syncthreads();

        float2 uh[8][2];
#pragma unroll
        for (int bb = 0; bb < 8; bb++) {
            uh[bb][0] = make_float2(0.f, 0.f);
            uh[bb][1] = make_float2(0.f, 0.f);
        }
#pragma unroll
        for (int j0 = 0; j0 < 16; j0 += 4) {
            float4 wv[4];
#pragma unroll
            for (int jj = 0; jj < 4; jj++)
                wv[jj] = *reinterpret_cast<const float4*>(&Ws[j0 + jj][cg * 4]);
#pragma unroll
            for (int bb = 0; bb < 8; bb++) {
                const float4 uv = *reinterpret_cast<const float4*>(&Us[bg * 8 + bb][j0]);
                const float uj[4] = {uv.x, uv.y, uv.z, uv.w};
#pragma unroll
                for (int jj = 0; jj < 4; jj++) {
                    const float2 us = make_float2(uj[jj], uj[jj]);
                    uh[bb][0] = ffma2(us, make_float2(wv[jj].x, wv[jj].y), uh[bb][0]);
                    uh[bb][1] = ffma2(us, make_float2(wv[jj].z, wv[jj].w), uh[bb][1]);
                }
            }
        }
#pragma unroll
        for (int bb = 0; bb < 8; bb++) {
            const float c = Cs[bg * 8 + bb][kq];
            const float2 cc = make_float2(c, c);
            acc[bb][0] = ffma2(cc, uh[bb][0], acc[bb][0]);
            acc[bb][1] = ffma2(cc, uh[bb][1], acc[bb][1]);
        }
    }
#pragma unroll
    for (int bb = 0; bb < 8; bb++) {
        float* dst = g_Uh + (size_t)(bg * 8 + bb) * KLc + k0 * 32 + cg * 4;
        atomicAdd(dst + 0, acc[bb][0].x);
        atomicAdd(dst + 1, acc[bb][0].y);
        atomicAdd(dst + 2, acc[bb][1].x);
        atomicAdd(dst + 3, acc[bb][1].y);
    }
}

// ---------------------------------------------------------------------------
// Squash: out[b,k,:] = (1 - 1/(exp(n)+eps)) * x/(n+eps),  n = ||U_h[b,k,:]||
// ---------------------------------------------------------------------------
__global__ void k_squash(float* __restrict__ out) {
    const int t = blockIdx.x * blockDim.x + threadIdx.x;  // b*32+k, 0..2047
    const float* x = g_Uh + (size_t)t * 32;
    float4 v[8];
    float ss = 0.f;
#pragma unroll
    for (int q = 0; q < 8; q++) {
        v[q] = *reinterpret_cast<const float4*>(x + q * 4);
        ss += v[q].x * v[q].x + v[q].y * v[q].y + v[q].z * v[q].z + v[q].w * v[q].w;
    }
    const float n = sqrtf(ss);
    const float coef = (1.f - 1.f / (expf(n) + 1e-20f)) / (n + 1e-20f);
    float* o = out + (size_t)t * 32;
#pragma unroll
    for (int q = 0; q < 8; q++) {
        float4 r;
        r.x = v[q].x * coef; r.y = v[q].y * coef;
        r.z = v[q].z * coef; r.w = v[q].w * coef;
        *reinterpret_cast<float4*>(o + q * 4) = r;
    }
}

// ---------------------------------------------------------------------------
extern "C" void kernel_launch(void* const* d_in, const int* in_sizes, int n_in,
                              void* d_out, int out_size) {
    const float* U = (const float*)d_in[0];
    const float* W = (const float*)d_in[1];
    float* out = (float*)d_out;

    cudaFuncSetAttribute(k_pass2a, cudaFuncAttributeMaxDynamicSharedMemorySize,
                         SM2A_BYTES);

    k_zero<<<64, 256>>>();
    k_pass1<<<dim3(8, 16), 256>>>(U, W);
    k_pass2a<<<NLc, 256, SM2A_BYTES>>>(U, W);
    k_pass2b<<<dim3(8, 16), 256>>>(U, W);
    k_squash<<<8, 256>>>(out);
}

// round 3
// speedup vs baseline: 1.1000x; 1.1000x over previous
#include <cuda_runtime.h>
#include <cstddef>

// Problem: B=64, n_l=512, n_h=32, d_l=16, d_h=32
#define Bsz 64
#define NLc 512
#define NHc 32
#define DLc 16
#define KLc 1024   // NH*DH
#define INV_SCALE 0.17677669529663687f  // 1/sqrt(32)

// Static scratch (no allocations allowed)
__device__ float g_S[Bsz * KLc];          // S[b][k*32+l]
__device__ float g_C[Bsz * NLc * NHc];    // C[b][i][k]
__device__ float g_Uh[Bsz * KLc];         // U_h accumulator

// Packed fp32x2 FMA (sm_100+): 2x fp32 FMA throughput
__device__ __forceinline__ float2 ffma2(float2 a, float2 b, float2 c) {
    float2 d;
    asm("{\n\t"
        ".reg .b64 ra, rb, rc, rd;\n\t"
        "mov.b64 ra, {%2, %3};\n\t"
        "mov.b64 rb, {%4, %5};\n\t"
        "mov.b64 rc, {%6, %7};\n\t"
        "fma.rn.f32x2 rd, ra, rb, rc;\n\t"
        "mov.b64 {%0, %1}, rd;\n\t"
        "}"
        : "=f"(d.x), "=f"(d.y)
        : "f"(a.x), "f"(a.y), "f"(b.x), "f"(b.y), "f"(c.x), "f"(c.y));
    return d;
}

__device__ __forceinline__ unsigned smem_u32(const void* p) {
    return (unsigned)__cvta_generic_to_shared(p);
}
#define CP_ASYNC16(dst, src) \
    asm volatile("cp.async.ca.shared.global [%0], [%1], 16;" ::"r"(dst), "l"(src))
#define CP_COMMIT() asm volatile("cp.async.commit_group;")
#define CP_WAIT1() asm volatile("cp.async.wait_group 1;" ::: "memory")
#define CP_WAIT0() asm volatile("cp.async.wait_group 0;" ::: "memory")

// ---------------------------------------------------------------------------
// Zero accumulators (replayed each graph launch)
// ---------------------------------------------------------------------------
__global__ void k_zero() {
    const int t = blockIdx.x * blockDim.x + threadIdx.x;  // 0..16383
    const float4 z = make_float4(0.f, 0.f, 0.f, 0.f);
    *reinterpret_cast<float4*>(g_S + (size_t)t * 4) = z;
    *reinterpret_cast<float4*>(g_Uh + (size_t)t * 4) = z;
}

// ---------------------------------------------------------------------------
// Pass 1: S[b][k*32+l] = sum_{i,j} U[b,i*16+j] * W[i,k,j,l]
// Grid (8 col-tiles of 128, 32 i-chunks of 16), 256 thr, tile 8b x 4c.
// Double-buffered cp.async pipeline over i.
// ---------------------------------------------------------------------------
#define NIT1 16

__device__ __forceinline__ void stage_tiles(const float* __restrict__ U,
                                            const float* __restrict__ W,
                                            int i, int k0, int tx,
                                            float (*Us)[DLc], float (*Ws)[132]) {
    {   // U tile: 64x16 = 256 float4, one per thread
        const int b = tx >> 2, j4 = (tx & 3) * 4;
        CP_ASYNC16(smem_u32(&Us[b][j4]),
                   U + (size_t)b * 8192 + (size_t)i * 16 + j4);
    }
    {   // W tile: 16x128 = 512 float4, two per thread (coalesced)
        const float* Wi = W + (size_t)i * 16384 + (size_t)k0 * 512;
#pragma unroll
        for (int r = 0; r < 2; r++) {
            const int v = tx + r * 256;       // float4 index 0..511
            const int kk = v >> 7;            // 0..3
            const int rem = v & 127;
            const int j = rem >> 3;
            const int l4 = (rem & 7) * 4;
            CP_ASYNC16(smem_u32(&Ws[j][kk * 32 + l4]),
                       Wi + kk * 512 + j * 32 + l4);
        }
    }
}

__global__ void __launch_bounds__(256, 2) k_pass1(const float* __restrict__ U,
                                                  const float* __restrict__ W) {
    __shared__ float Us[2][Bsz][DLc];
    __shared__ float Ws[2][DLc][132];
    const int tx = threadIdx.x;
    const int cg = tx & 31;            // col-group: 4 cols each
    const int bg = tx >> 5;            // b-group: 8 b each
    const int k0 = blockIdx.x * 4;
    const int i0 = blockIdx.y * NIT1;

    float2 acc[8][2];
#pragma unroll
    for (int bb = 0; bb < 8; bb++) {
        acc[bb][0] = make_float2(0.f, 0.f);
        acc[bb][1] = make_float2(0.f, 0.f);
    }

    stage_tiles(U, W, i0, k0, tx, Us[0], Ws[0]);
    CP_COMMIT();

    int s = 0;
    for (int it = 0; it < NIT1; it++) {
        if (it + 1 < NIT1) {
            stage_tiles(U, W, i0 + it + 1, k0, tx, Us[s ^ 1], Ws[s ^ 1]);
            CP_COMMIT();
            CP_WAIT1();
        } else {
            CP_WAIT0();
        }
        __syncthreads();
#pragma unroll
        for (int j0 = 0; j0 < 16; j0 += 4) {
            float4 wv[4];
#pragma unroll
            for (int jj = 0; jj < 4; jj++)
                wv[jj] = *reinterpret_cast<const float4*>(&Ws[s][j0 + jj][cg * 4]);
#pragma unroll
            for (int bb = 0; bb < 8; bb++) {
                const float4 uv =
                    *reinterpret_cast<const float4*>(&Us[s][bg * 8 + bb][j0]);
                const float uj[4] = {uv.x, uv.y, uv.z, uv.w};
#pragma unroll
                for (int jj = 0; jj < 4; jj++) {
                    const float2 us = make_float2(uj[jj], uj[jj]);
                    acc[bb][0] = ffma2(us, make_float2(wv[jj].x, wv[jj].y), acc[bb][0]);
                    acc[bb][1] = ffma2(us, make_float2(wv[jj].z, wv[jj].w), acc[bb][1]);
                }
            }
        }
        s ^= 1;
        __syncthreads();
    }
#pragma unroll
    for (int bb = 0; bb < 8; bb++) {
        float* dst = g_S + (size_t)(bg * 8 + bb) * KLc + k0 * 32 + cg * 4;
        atomicAdd(dst + 0, acc[bb][0].x);
        atomicAdd(dst + 1, acc[bb][0].y);
        atomicAdd(dst + 2, acc[bb][1].x);
        atomicAdd(dst + 3, acc[bb][1].y);
    }
}

// ---------------------------------------------------------------------------
// Pass 2a: per i: recompute u_hat[b,k,:], A_sum[b,k] = dot(u_hat, S[b,k,:]),
// softmax over k -> C[b,i,k]. W[i] staged in dynamic SMEM via cp.async.
// ---------------------------------------------------------------------------
#define WPAD 36
#define WS2A (512 * WPAD)
#define SM2A_FLOATS (WS2A + Bsz * DLc + Bsz * NHc)
#define SM2A_BYTES (SM2A_FLOATS * 4)                 // 86016 B

__global__ void __launch_bounds__(256) k_pass2a(const float* __restrict__ U,
                                                const float* __restrict__ W) {
    extern __shared__ float sm[];
    float* Ws  = sm;                      // [(j*32 + k)*WPAD + l]
    float* Us  = sm + WS2A;               // [b*16 + j]
    float* Asm = Us + Bsz * DLc;          // [b*32 + k]
    const int tx = threadIdx.x;
    const int i = blockIdx.x;

    {   // W[i]: 4096 float4, 16 per thread, via cp.async
        const float* Wi = W + (size_t)i * 16384;
#pragma unroll
        for (int r = 0; r < 16; r++) {
            const int g = (tx + r * 256) * 4;
            const int k = g >> 9;
            const int j = (g >> 5) & 15;
            const int l = g & 31;
            CP_ASYNC16(smem_u32(Ws + (j * 32 + k) * WPAD + l), Wi + g);
        }
    }
    {
        const int b = tx >> 2, j4 = (tx & 3) * 4;
        CP_ASYNC16(smem_u32(Us + b * 16 + j4),
                   U + (size_t)b * 8192 + (size_t)i * 16 + j4);
    }
    CP_COMMIT();
    CP_WAIT0();
    __syncthreads();

    const int kk = tx & 15;
    const int bg = tx >> 4;   // 16 groups of 4 b
#pragma unroll
    for (int kh = 0; kh < 2; kh++) {
        const int k = kk + kh * 16;
        float a[4] = {0.f, 0.f, 0.f, 0.f};
#pragma unroll
        for (int lh = 0; lh < 2; lh++) {
            const int l0 = lh * 16;
            float2 uh[4][8];
#pragma unroll
            for (int bb = 0; bb < 4; bb++)
#pragma unroll
                for (int p = 0; p < 8; p++) uh[bb][p] = make_float2(0.f, 0.f);
#pragma unroll
            for (int j = 0; j < 16; j++) {
                const float* wrow = Ws + (j * 32 + k) * WPAD + l0;
                float2 wp[8];
#pragma unroll
                for (int q = 0; q < 4; q++) {
                    const float4 w4 = *reinterpret_cast<const float4*>(wrow + q * 4);
                    wp[2 * q]     = make_float2(w4.x, w4.y);
                    wp[2 * q + 1] = make_float2(w4.z, w4.w);
                }
#pragma unroll
                for (int bb = 0; bb < 4; bb++) {
                    const float u = Us[(bg * 4 + bb) * 16 + j];
                    const float2 us = make_float2(u, u);
#pragma unroll
                    for (int p = 0; p < 8; p++) uh[bb][p] = ffma2(us, wp[p], uh[bb][p]);
                }
            }
#pragma unroll
            for (int bb = 0; bb < 4; bb++) {
                const float* Sp = g_S + (size_t)(bg * 4 + bb) * KLc + k * 32 + l0;
#pragma unroll
                for (int q = 0; q < 4; q++) {
                    const float4 s4 = *reinterpret_cast<const float4*>(Sp + q * 4);
                    a[bb] += uh[bb][2 * q].x * s4.x + uh[bb][2 * q].y * s4.y
                           + uh[bb][2 * q + 1].x * s4.z + uh[bb][2 * q + 1].y * s4.w;
                }
            }
        }
#pragma unroll
        for (int bb = 0; bb < 4; bb++) Asm[(bg * 4 + bb) * 32 + k] = a[bb];
    }
    __syncthreads();

    if (tx < Bsz) {
        const int b = tx;
        float v[32];
        float m = -3.4e38f;
#pragma unroll
        for (int k = 0; k < 32; k++) { v[k] = Asm[b * 32 + k]; m = fmaxf(m, v[k]); }
        float s = 0.f;
#pragma unroll
        for (int k = 0; k < 32; k++) { v[k] = __expf((v[k] - m) * INV_SCALE); s += v[k]; }
        const float inv = 1.f / s;
        float* Cp = g_C + ((size_t)b * NLc + i) * NHc;
#pragma unroll
        for (int k = 0; k < 32; k++) Cp[k] = v[k] * inv;
    }
}

// ---------------------------------------------------------------------------
// Pass 2b: U_h[b][k*32+l] = sum_i C[b,i,k] * u_hat[b,i,k,l]
// Pass-1 pipeline skeleton with per-i C-weighting.
// ---------------------------------------------------------------------------
__global__ void __launch_bounds__(256, 2) k_pass2b(const float* __restrict__ U,
                                                   const float* __restrict__ W) {
    __shared__ float Us[2][Bsz][DLc];
    __shared__ float Ws[2][DLc][132];
    __shared__ float Cs[2][Bsz][4];
    const int tx = threadIdx.x;
    const int cg = tx & 31;
    const int bg = tx >> 5;
    const int k0 = blockIdx.x * 4;
    const int i0 = blockIdx.y * NIT1;
    const int kq = cg >> 3;

    float2 acc[8][2];
#pragma unroll
    for (int bb = 0; bb < 8; bb++) {
        acc[bb][0] = make_float2(0.f, 0.f);
        acc[bb][1] = make_float2(0.f, 0.f);
    }

    // stage i0 into buffer 0 (tiles + C)
    stage_tiles(U, W, i0, k0, tx, Us[0], Ws[0]);
    if (tx < Bsz)
        CP_ASYNC16(smem_u32(&Cs[0][tx][0]),
                   g_C + ((size_t)tx * NLc + i0) * NHc + k0);
    CP_COMMIT();

    int s = 0;
    for (int it = 0; it < NIT1; it++) {
        if (it + 1 < NIT1) {
            const int inx = i0 + it + 1;
            stage_tiles(U, W, inx, k0, tx, Us[s ^ 1], Ws[s ^ 1]);
            if (tx < Bsz)
                CP_ASYNC16(smem_u32(&Cs[s ^ 1][tx][0]),
                           g_C + ((size_t)tx * NLc + inx) * NHc + k0);
            CP_COMMIT();
            CP_WAIT1();
        } else {
            CP_WAIT0();
        }
        __syncthreads();

        float2 uh[8][2];
#pragma unroll
        for (int bb = 0; bb < 8; bb++) {
            uh[bb][0] = make_float2(0.f, 0.f);
            uh[bb][1] = make_float2(0.f, 0.f);
        }
#pragma unroll
        for (int j0 = 0; j0 < 16; j0 += 4) {
            float4 wv[4];
#pragma unroll
            for (int jj = 0; jj < 4; jj++)
                wv[jj] = *reinterpret_cast<const float4*>(&Ws[s][j0 + jj][cg * 4]);
#pragma unroll
            for (int bb = 0; bb < 8; bb++) {
                const float4 uv =
                    *reinterpret_cast<const float4*>(&Us[s][bg * 8 + bb][j0]);
                const float uj[4] = {uv.x, uv.y, uv.z, uv.w};
#pragma unroll
                for (int jj = 0; jj < 4; jj++) {
                    const float2 us = make_float2(uj[jj], uj[jj]);
                    uh[bb][0] = ffma2(us, make_float2(wv[jj].x, wv[jj].y), uh[bb][0]);
                    uh[bb][1] = ffma2(us, make_float2(wv[jj].z, wv[jj].w), uh[bb][1]);
                }
            }
        }
#pragma unroll
        for (int bb = 0; bb < 8; bb++) {
            const float c = Cs[s][bg * 8 + bb][kq];
            const float2 cc = make_float2(c, c);
            acc[bb][0] = ffma2(cc, uh[bb][0], acc[bb][0]);
            acc[bb][1] = ffma2(cc, uh[bb][1], acc[bb][1]);
        }
        s ^= 1;
        __syncthreads();
    }
#pragma unroll
    for (int bb = 0; bb < 8; bb++) {
        float* dst = g_Uh + (size_t)(bg * 8 + bb) * KLc + k0 * 32 + cg * 4;
        atomicAdd(dst + 0, acc[bb][0].x);
        atomicAdd(dst + 1, acc[bb][0].y);
        atomicAdd(dst + 2, acc[bb][1].x);
        atomicAdd(dst + 3, acc[bb][1].y);
    }
}

// ---------------------------------------------------------------------------
// Squash
// ---------------------------------------------------------------------------
__global__ void k_squash(float* __restrict__ out) {
    const int t = blockIdx.x * blockDim.x + threadIdx.x;  // b*32+k
    const float* x = g_Uh + (size_t)t * 32;
    float4 v[8];
    float ss = 0.f;
#pragma unroll
    for (int q = 0; q < 8; q++) {
        v[q] = *reinterpret_cast<const float4*>(x + q * 4);
        ss += v[q].x * v[q].x + v[q].y * v[q].y + v[q].z * v[q].z + v[q].w * v[q].w;
    }
    const float n = sqrtf(ss);
    const float coef = (1.f - 1.f / (expf(n) + 1e-20f)) / (n + 1e-20f);
    float* o = out + (size_t)t * 32;
#pragma unroll
    for (int q = 0; q < 8; q++) {
        float4 r;
        r.x = v[q].x * coef; r.y = v[q].y * coef;
        r.z = v[q].z * coef; r.w = v[q].w * coef;
        *reinterpret_cast<float4*>(o + q * 4) = r;
    }
}

// ---------------------------------------------------------------------------
extern "C" void kernel_launch(void* const* d_in, const int* in_sizes, int n_in,
                              void* d_out, int out_size) {
    const float* U = (const float*)d_in[0];
    const float* W = (const float*)d_in[1];
    float* out = (float*)d_out;

    cudaFuncSetAttribute(k_pass2a, cudaFuncAttributeMaxDynamicSharedMemorySize,
                         SM2A_BYTES);

    k_zero<<<64, 256>>>();
    k_pass1<<<dim3(8, 32), 256>>>(U, W);
    k_pass2a<<<NLc, 256, SM2A_BYTES>>>(U, W);
    k_pass2b<<<dim3(8, 32), 256>>>(U, W);
    k_squash<<<8, 256>>>(out);
}

// round 4
// speedup vs baseline: 1.3281x; 1.2074x over previous
#include <cuda_runtime.h>
#include <cstddef>

// Problem: B=64, n_l=512, n_h=32, d_l=16, d_h=32
#define Bsz 64
#define NLc 512
#define NHc 32
#define DLc 16
#define KLc 1024   // NH*DH
#define INV_SCALE 0.17677669529663687f  // 1/sqrt(32)

// Static scratch (no allocations allowed)
__device__ float g_S[Bsz * KLc];          // S[b][k*32+l]
__device__ float g_Uh[Bsz * KLc];         // U_h accumulator

// Packed fp32x2 FMA (sm_100+)
__device__ __forceinline__ float2 ffma2(float2 a, float2 b, float2 c) {
    float2 d;
    asm("{\n\t"
        ".reg .b64 ra, rb, rc, rd;\n\t"
        "mov.b64 ra, {%2, %3};\n\t"
        "mov.b64 rb, {%4, %5};\n\t"
        "mov.b64 rc, {%6, %7};\n\t"
        "fma.rn.f32x2 rd, ra, rb, rc;\n\t"
        "mov.b64 {%0, %1}, rd;\n\t"
        "}"
        : "=f"(d.x), "=f"(d.y)
        : "f"(a.x), "f"(a.y), "f"(b.x), "f"(b.y), "f"(c.x), "f"(c.y));
    return d;
}

__device__ __forceinline__ unsigned smem_u32(const void* p) {
    return (unsigned)__cvta_generic_to_shared(p);
}
#define CP_ASYNC16(dst, src) \
    asm volatile("cp.async.ca.shared.global [%0], [%1], 16;" ::"r"(dst), "l"(src))
#define CP_COMMIT() asm volatile("cp.async.commit_group;")
#define CP_WAIT1() asm volatile("cp.async.wait_group 1;" ::: "memory")
#define CP_WAIT0() asm volatile("cp.async.wait_group 0;" ::: "memory")

// ---------------------------------------------------------------------------
__global__ void k_zero() {
    const int t = blockIdx.x * blockDim.x + threadIdx.x;  // 0..16383
    const float4 z = make_float4(0.f, 0.f, 0.f, 0.f);
    *reinterpret_cast<float4*>(g_S + (size_t)t * 4) = z;
    *reinterpret_cast<float4*>(g_Uh + (size_t)t * 4) = z;
}

// ---------------------------------------------------------------------------
// Pass 1: S[b][k*32+l] = sum_{i,j} U[b,i*16+j] * W[i,k,j,l]
// ---------------------------------------------------------------------------
#define NIT1 16

__device__ __forceinline__ void stage_tiles(const float* __restrict__ U,
                                            const float* __restrict__ W,
                                            int i, int k0, int tx,
                                            float (*Us)[DLc], float (*Ws)[132]) {
    {
        const int b = tx >> 2, j4 = (tx & 3) * 4;
        CP_ASYNC16(smem_u32(&Us[b][j4]),
                   U + (size_t)b * 8192 + (size_t)i * 16 + j4);
    }
    {
        const float* Wi = W + (size_t)i * 16384 + (size_t)k0 * 512;
#pragma unroll
        for (int r = 0; r < 2; r++) {
            const int v = tx + r * 256;
            const int kk = v >> 7;
            const int rem = v & 127;
            const int j = rem >> 3;
            const int l4 = (rem & 7) * 4;
            CP_ASYNC16(smem_u32(&Ws[j][kk * 32 + l4]),
                       Wi + kk * 512 + j * 32 + l4);
        }
    }
}

__global__ void __launch_bounds__(256, 2) k_pass1(const float* __restrict__ U,
                                                  const float* __restrict__ W) {
    __shared__ float Us[2][Bsz][DLc];
    __shared__ float Ws[2][DLc][132];
    const int tx = threadIdx.x;
    const int cg = tx & 31;
    const int bg = tx >> 5;
    const int k0 = blockIdx.x * 4;
    const int i0 = blockIdx.y * NIT1;

    float2 acc[8][2];
#pragma unroll
    for (int bb = 0; bb < 8; bb++) {
        acc[bb][0] = make_float2(0.f, 0.f);
        acc[bb][1] = make_float2(0.f, 0.f);
    }

    stage_tiles(U, W, i0, k0, tx, Us[0], Ws[0]);
    CP_COMMIT();

    int s = 0;
    for (int it = 0; it < NIT1; it++) {
        if (it + 1 < NIT1) {
            stage_tiles(U, W, i0 + it + 1, k0, tx, Us[s ^ 1], Ws[s ^ 1]);
            CP_COMMIT();
            CP_WAIT1();
        } else {
            CP_WAIT0();
        }
        __syncthreads();
#pragma unroll
        for (int j0 = 0; j0 < 16; j0 += 4) {
            float4 wv[4];
#pragma unroll
            for (int jj = 0; jj < 4; jj++)
                wv[jj] = *reinterpret_cast<const float4*>(&Ws[s][j0 + jj][cg * 4]);
#pragma unroll
            for (int bb = 0; bb < 8; bb++) {
                const float4 uv =
                    *reinterpret_cast<const float4*>(&Us[s][bg * 8 + bb][j0]);
                const float uj[4] = {uv.x, uv.y, uv.z, uv.w};
#pragma unroll
                for (int jj = 0; jj < 4; jj++) {
                    const float2 us = make_float2(uj[jj], uj[jj]);
                    acc[bb][0] = ffma2(us, make_float2(wv[jj].x, wv[jj].y), acc[bb][0]);
                    acc[bb][1] = ffma2(us, make_float2(wv[jj].z, wv[jj].w), acc[bb][1]);
                }
            }
        }
        s ^= 1;
        __syncthreads();
    }
#pragma unroll
    for (int bb = 0; bb < 8; bb++) {
        float* dst = g_S + (size_t)(bg * 8 + bb) * KLc + k0 * 32 + cg * 4;
        atomicAdd(dst + 0, acc[bb][0].x);
        atomicAdd(dst + 1, acc[bb][0].y);
        atomicAdd(dst + 2, acc[bb][1].x);
        atomicAdd(dst + 3, acc[bb][1].y);
    }
}

// ---------------------------------------------------------------------------
// Fused pass 2: per (b-slice of 16, chunk of 16 i):
//   u_hat in regs -> logits dot S -> softmax -> C-weighted accumulate -> REDs
// ---------------------------------------------------------------------------
#define FNI 16
// SMEM float offsets
#define FSM_SS   (2 * 16384)            // after Ws[2][16][1024]
#define FSM_US   (FSM_SS + 16384)       // Usm[2][256]
#define FSM_ASM  (FSM_US + 512)         // Asm[16][33]
#define FSM_CSM  (FSM_ASM + 16 * 33)    // Csm[16][33]
#define FSM_TOT  (FSM_CSM + 16 * 33)
#define FSM_BYTES (FSM_TOT * 4)         // 202880 B

// Chunk swizzle: c = k*8 + lg*2 + e  ->  [k4..k1][e][k0][lg1 lg0]
// Guarantees each quarter-warp's LDS.128 hits 8 distinct bank groups.
__device__ __forceinline__ int wswz(int c) {
    const int k = c >> 3, lg = (c >> 1) & 3, e = c & 1;
    return ((k >> 1) << 4) | (e << 3) | ((k & 1) << 2) | lg;
}

__device__ __forceinline__ void f_stage_w(const float* __restrict__ Wi,
                                          float* dst, int tx) {
#pragma unroll
    for (int r = 0; r < 8; r++) {
        const int idx = tx + r * 512;          // float4 idx 0..4095
        const int k = idx >> 7, j = (idx >> 3) & 15, lq = idx & 7;
        const int c = k * 8 + lq;
        CP_ASYNC16(smem_u32(dst + j * 1024 + wswz(c) * 4),
                   Wi + (size_t)idx * 4);
    }
}
__device__ __forceinline__ void f_stage_u(const float* __restrict__ U,
                                          float* dst, int b0, int i, int tx) {
    if (tx < 64) {
        const int bb = tx >> 2, j4 = (tx & 3) * 4;
        CP_ASYNC16(smem_u32(dst + bb * 16 + j4),
                   U + (size_t)(b0 + bb) * 8192 + (size_t)i * 16 + j4);
    }
}

__global__ void __launch_bounds__(512, 1)
k_fused(const float* __restrict__ U, const float* __restrict__ W) {
    extern __shared__ float sm[];
    float* Ws  = sm;                 // [buf][j][1024 swizzled]
    float* Ss  = sm + FSM_SS;        // [bb][1024 swizzled]
    float* Usm = sm + FSM_US;        // [buf][bb*16+j]
    float* Asm = sm + FSM_ASM;       // [bb][33]
    float* Csm = sm + FSM_CSM;       // [bb][33]

    const int tx = threadIdx.x;
    const int w = tx >> 5;                       // warp 0..15
    const int lane = tx & 31;
    const int bg = lane >> 3;                    // 4 b-groups inside the warp
    const int kk = w * 2 + ((lane >> 2) & 1);    // k 0..31
    const int lg = lane & 3;                     // l-octet group
    const int b0 = blockIdx.y * 16;
    const int i0 = blockIdx.x * FNI;

    // chunk offsets for this thread's (kk, lg)
    const int c0 = ((kk >> 1) << 4) | ((kk & 1) << 2) | lg;   // e=0
    const int c1 = c0 | 8;                                    // e=1

    // stage S slice + first W/U
#pragma unroll
    for (int r = 0; r < 8; r++) {
        const int idx = tx + r * 512;
        const int bb = idx >> 8, c = idx & 255;
        CP_ASYNC16(smem_u32(Ss + bb * 1024 + wswz(c) * 4),
                   g_S + (size_t)(b0 + bb) * KLc + c * 4);
    }
    f_stage_w(W + (size_t)i0 * 16384, Ws, tx);
    f_stage_u(U, Usm, b0, i0, tx);
    CP_COMMIT();

    float2 acc[4][4];
#pragma unroll
    for (int bb = 0; bb < 4; bb++)
#pragma unroll
        for (int p = 0; p < 4; p++) acc[bb][p] = make_float2(0.f, 0.f);

    int s = 0;
    for (int it = 0; it < FNI; it++) {
        if (it + 1 < FNI) {
            f_stage_w(W + (size_t)(i0 + it + 1) * 16384, Ws + (s ^ 1) * 16384, tx);
            f_stage_u(U, Usm + (s ^ 1) * 256, b0, i0 + it + 1, tx);
            CP_COMMIT();
            CP_WAIT1();
        } else {
            CP_WAIT0();
        }
        __syncthreads();

        const float* Wb = Ws + s * 16384;
        const float* Ub = Usm + s * 256;

        // u_hat for (4 b, k=kk, l = lg*8..lg*8+7), kept in registers
        float2 uh[4][4];
#pragma unroll
        for (int bb = 0; bb < 4; bb++)
#pragma unroll
            for (int p = 0; p < 4; p++) uh[bb][p] = make_float2(0.f, 0.f);
#pragma unroll
        for (int j = 0; j < 16; j++) {
            const float* wj = Wb + j * 1024;
            const float4 w0 = *reinterpret_cast<const float4*>(wj + c0 * 4);
            const float4 w1 = *reinterpret_cast<const float4*>(wj + c1 * 4);
            const float2 wp0 = make_float2(w0.x, w0.y);
            const float2 wp1 = make_float2(w0.z, w0.w);
            const float2 wp2 = make_float2(w1.x, w1.y);
            const float2 wp3 = make_float2(w1.z, w1.w);
#pragma unroll
            for (int bb = 0; bb < 4; bb++) {
                const float u = Ub[(bg * 4 + bb) * 16 + j];
                const float2 us = make_float2(u, u);
                uh[bb][0] = ffma2(us, wp0, uh[bb][0]);
                uh[bb][1] = ffma2(us, wp1, uh[bb][1]);
                uh[bb][2] = ffma2(us, wp2, uh[bb][2]);
                uh[bb][3] = ffma2(us, wp3, uh[bb][3]);
            }
        }

        // logits: a[bb] = dot(u_hat, S[b,kk,:]) over this thread's 8 l
        float a[4];
#pragma unroll
        for (int bb = 0; bb < 4; bb++) {
            const float* sp = Ss + (bg * 4 + bb) * 1024;
            const float4 s0 = *reinterpret_cast<const float4*>(sp + c0 * 4);
            const float4 s1 = *reinterpret_cast<const float4*>(sp + c1 * 4);
            a[bb] = uh[bb][0].x * s0.x + uh[bb][0].y * s0.y
                  + uh[bb][1].x * s0.z + uh[bb][1].y * s0.w
                  + uh[bb][2].x * s1.x + uh[bb][2].y * s1.y
                  + uh[bb][3].x * s1.z + uh[bb][3].y * s1.w;
        }
#pragma unroll
        for (int bb = 0; bb < 4; bb++) {
            a[bb] += __shfl_xor_sync(0xffffffffu, a[bb], 1);
            a[bb] += __shfl_xor_sync(0xffffffffu, a[bb], 2);
        }
        if (lg == 0) {
#pragma unroll
            for (int bb = 0; bb < 4; bb++)
                Asm[(bg * 4 + bb) * 33 + kk] = a[bb];
        }
        __syncthreads();

        // softmax over k: warp w owns b-local row w, lane = k
        {
            const float v = Asm[w * 33 + lane];
            float m = v;
#pragma unroll
            for (int o = 16; o; o >>= 1)
                m = fmaxf(m, __shfl_xor_sync(0xffffffffu, m, o));
            const float ev = __expf((v - m) * INV_SCALE);
            float ssum = ev;
#pragma unroll
            for (int o = 16; o; o >>= 1)
                ssum += __shfl_xor_sync(0xffffffffu, ssum, o);
            Csm[w * 33 + lane] = ev / ssum;
        }
        __syncthreads();

        // C-weighted accumulation (u_hat still in registers)
#pragma unroll
        for (int bb = 0; bb < 4; bb++) {
            const float cw = Csm[(bg * 4 + bb) * 33 + kk];
            const float2 cc = make_float2(cw, cw);
#pragma unroll
            for (int p = 0; p < 4; p++)
                acc[bb][p] = ffma2(cc, uh[bb][p], acc[bb][p]);
        }
        s ^= 1;
    }

    // flush accumulators (32 adds per address chip-wide)
#pragma unroll
    for (int bb = 0; bb < 4; bb++) {
        float* dst = g_Uh + (size_t)(b0 + bg * 4 + bb) * KLc + kk * 32 + lg * 8;
        atomicAdd(dst + 0, acc[bb][0].x);
        atomicAdd(dst + 1, acc[bb][0].y);
        atomicAdd(dst + 2, acc[bb][1].x);
        atomicAdd(dst + 3, acc[bb][1].y);
        atomicAdd(dst + 4, acc[bb][2].x);
        atomicAdd(dst + 5, acc[bb][2].y);
        atomicAdd(dst + 6, acc[bb][3].x);
        atomicAdd(dst + 7, acc[bb][3].y);
    }
}

// ---------------------------------------------------------------------------
// Squash
// ---------------------------------------------------------------------------
__global__ void k_squash(float* __restrict__ out) {
    const int t = blockIdx.x * blockDim.x + threadIdx.x;  // b*32+k
    const float* x = g_Uh + (size_t)t * 32;
    float4 v[8];
    float ss = 0.f;
#pragma unroll
    for (int q = 0; q < 8; q++) {
        v[q] = *reinterpret_cast<const float4*>(x + q * 4);
        ss += v[q].x * v[q].x + v[q].y * v[q].y + v[q].z * v[q].z + v[q].w * v[q].w;
    }
    const float n = sqrtf(ss);
    const float coef = (1.f - 1.f / (expf(n) + 1e-20f)) / (n + 1e-20f);
    float* o = out + (size_t)t * 32;
#pragma unroll
    for (int q = 0; q < 8; q++) {
        float4 r;
        r.x = v[q].x * coef; r.y = v[q].y * coef;
        r.z = v[q].z * coef; r.w = v[q].w * coef;
        *reinterpret_cast<float4*>(o + q * 4) = r;
    }
}

// ---------------------------------------------------------------------------
extern "C" void kernel_launch(void* const* d_in, const int* in_sizes, int n_in,
                              void* d_out, int out_size) {
    const float* U = (const float*)d_in[0];
    const float* W = (const float*)d_in[1];
    float* out = (float*)d_out;

    cudaFuncSetAttribute(k_fused, cudaFuncAttributeMaxDynamicSharedMemorySize,
                         FSM_BYTES);

    k_zero<<<64, 256>>>();
    k_pass1<<<dim3(8, 32), 256>>>(U, W);
    k_fused<<<dim3(32, 4), 512, FSM_BYTES>>>(U, W);
    k_squash<<<8, 256>>>(out);
}